// round 7
// baseline (speedup 1.0000x reference)
#include <cuda_runtime.h>
#include <cstdint>

#define EN 2048
#define IN_ 256
#define TN 256
#define BN 32
#define EWORDS 64
#define IWORDS 8
#define NT 1024     // threads per CTA (2 exc neurons each, stride 1024)
#define CHUNK 16

// persistent scratch (no allocation allowed)
__device__ __align__(16) uint32_t g_wrec_t[EWORDS * EN]; // transposed packed w_rec
__device__ float g_rowsum[EN];
__device__ float g_cs_wie[EN];    // sum_i w_ie[i][e] (ascending i)
__device__ float g_cs_wei[IN_];   // sum_e w_ei[e][i] (ascending e)
__device__ int      g_rsmin;
__device__ uint32_t g_cwie_max_u, g_cwei_min_u, g_xmax_u;
// persisted simulation state across chunk launches
__device__ float g_v[BN][EN], g_cu[BN][EN];
__device__ float g_iv[BN][IN_], g_ii[BN][IN_];
__device__ uint32_t g_ezb[BN][EWORDS], g_izb[BN][IWORDS];
__device__ uint32_t g_flags[BN];
__device__ int g_done[BN];        // saturation step ts (TN if never)

// ---------------- prep 1: pack w_rec bits + reset markers ----------------
__global__ void prep_pack(const float* __restrict__ wrec) {
    if (blockIdx.x == 0 && threadIdx.x < BN) {
        g_done[threadIdx.x] = TN;
        if (threadIdx.x == 0) {
            g_rsmin = 0x7fffffff;
            g_cwie_max_u = 0u;
            g_cwei_min_u = 0x7f7fffffu;
            g_xmax_u = 0u;
        }
    }
    int idx = blockIdx.x * blockDim.x + threadIdx.x;
    int j = idx >> 6, w = idx & 63;
    const uint4* p = reinterpret_cast<const uint4*>(wrec + (size_t)j * EN + (size_t)w * 32);
    uint32_t m = 0;
#pragma unroll
    for (int k = 0; k < 8; k++) {
        uint4 f = p[k];
        m |= (f.x ? 1u : 0u) << (k * 4 + 0);
        m |= (f.y ? 1u : 0u) << (k * 4 + 1);
        m |= (f.z ? 1u : 0u) << (k * 4 + 2);
        m |= (f.w ? 1u : 0u) << (k * 4 + 3);
    }
    g_wrec_t[w * EN + j] = m;
}

// ---------------- prep 2: sums + invariant bounds + max|x| ----------------
__global__ void prep_rest(const float* __restrict__ wie, const float* __restrict__ wei,
                          const float* __restrict__ x) {
    const int tid = threadIdx.x, lane = tid & 31;
    if (blockIdx.x < 8) {
        int t = blockIdx.x * 256 + tid;
        int c = 0;
#pragma unroll 8
        for (int w = 0; w < EWORDS; w++) c += __popc(g_wrec_t[w * EN + t]);
        g_rowsum[t] = (float)c;
        atomicMin(&g_rsmin, c);
        float s = 0.f;
#pragma unroll 4
        for (int i = 0; i < IN_; i++) s = __fadd_rn(s, wie[(size_t)i * EN + t]);
        g_cs_wie[t] = s;
        atomicMax(&g_cwie_max_u, __float_as_uint(s));
        if (t < IN_) {
            float q = 0.f;
#pragma unroll 4
            for (int e = 0; e < EN; e++) q = __fadd_rn(q, wei[(size_t)e * IN_ + t]);
            g_cs_wei[t] = q;
            atomicMin(&g_cwei_min_u, __float_as_uint(q));
        }
    } else {
        const float4* x4 = reinterpret_cast<const float4*>(x);
        const int n4 = (TN * BN * EN) / 4;
        int i = (blockIdx.x - 8) * 256 + tid;
        const int stride = 256 * 256;
        float m = 0.f;
        for (; i < n4; i += stride) {
            float4 f = x4[i];
            m = fmaxf(m, fmaxf(fmaxf(fabsf(f.x), fabsf(f.y)), fmaxf(fabsf(f.z), fabsf(f.w))));
        }
#pragma unroll
        for (int off = 16; off > 0; off >>= 1)
            m = fmaxf(m, __shfl_xor_sync(0xffffffffu, m, off));
        if (lane == 0) atomicMax(&g_xmax_u, __float_as_uint(m));
    }
}

// ---------------- sim chunk: 16 steps, one CTA per batch ----------------
__global__ __launch_bounds__(NT, 1)
void sim_chunk(const float* __restrict__ x,
               const float* __restrict__ wei,
               const float* __restrict__ wie,
               float* __restrict__ out, int t0)
{
    __shared__ uint32_t s_ez[2][EWORDS];
    __shared__ uint32_t s_iz[2][IWORDS];
    __shared__ __align__(16) unsigned char s_fb[2][32];

    const int tid  = threadIdx.x;
    const int b    = blockIdx.x;
    const int warp = tid >> 5, lane = tid & 31;

    if (g_done[b] < t0) return;   // already saturated: fill kernel owns these rows

    float v0, v1, c0, c1, iv = 0.f, ii = 0.f;
    int pe_all, pe_any, pi_all, pi_any;
    if (t0 == 0) {
        v0 = v1 = c0 = c1 = 0.f;
        pe_all = pe_any = pi_all = pi_any = 0;
        if (tid < EWORDS) s_ez[1][tid] = 0u;
        if (tid < IWORDS) s_iz[1][tid] = 0u;
    } else {
        v0 = g_v[b][tid];  v1 = g_v[b][tid + NT];
        c0 = g_cu[b][tid]; c1 = g_cu[b][tid + NT];
        if (tid < IN_) { iv = g_iv[b][tid]; ii = g_ii[b][tid]; }
        uint32_t fl = g_flags[b];
        pe_all = fl & 1; pe_any = (fl >> 1) & 1; pi_all = (fl >> 2) & 1; pi_any = (fl >> 3) & 1;
        if (tid < EWORDS) s_ez[1][tid] = g_ezb[b][tid];
        if (tid < IWORDS) s_iz[1][tid] = g_izb[b][tid];
    }

    const float rs0 = g_rowsum[tid], rs1 = g_rowsum[tid + NT];
    const float cw0 = g_cs_wie[tid], cw1 = g_cs_wie[tid + NT];
    const float cwei = (tid < IN_) ? g_cs_wei[tid] : 0.f;
    // saturation invariant enabling condition (proven sufficient)
    const int g_ok =
        (__fadd_rn((float)g_rsmin,
                   -__fadd_rn(__uint_as_float(g_cwie_max_u), __uint_as_float(g_xmax_u))) >= 13.0f)
        && (__uint_as_float(g_cwei_min_u) >= 13.0f);

    __syncthreads();

    int saturated = 0;
    int ne_all = pe_all, ne_any = pe_any, ni_all = pi_all, ni_any = pi_any;

    for (int t = t0; t < t0 + CHUNK; t++) {
        const int wp = t & 1, rp = wp ^ 1;

        // ---- [a] cross terms from previous step's spikes ----
        float rec0, rec1, inh0, inh1;
        if (pe_all)       { rec0 = rs0; rec1 = rs1; }
        else if (!pe_any) { rec0 = 0.f; rec1 = 0.f; }
        else {
            int a0 = 0, a1 = 0;
#pragma unroll 8
            for (int w = 0; w < EWORDS; w++) {
                uint32_t ez = s_ez[rp][w];
                a0 += __popc(ez & g_wrec_t[w * EN + tid]);
                a1 += __popc(ez & g_wrec_t[w * EN + tid + NT]);
            }
            rec0 = (float)a0; rec1 = (float)a1;
        }
        if (pi_all)       { inh0 = cw0; inh1 = cw1; }
        else if (!pi_any) { inh0 = 0.f; inh1 = 0.f; }
        else {
            inh0 = 0.f; inh1 = 0.f;
            for (int w = 0; w < IWORDS; w++) {
                uint32_t m = s_iz[rp][w];
                while (m) {
                    int cbit = __ffs(m) - 1; m &= m - 1;
                    const float* wr = wie + (size_t)(w * 32 + cbit) * EN + tid;
                    inh0 = __fadd_rn(inh0, wr[0]);
                    inh1 = __fadd_rn(inh1, wr[NT]);
                }
            }
        }

        // ---- [b] excitatory update (JAX-exact rounding order) ----
        float xc0 = __ldg(x + ((size_t)t * BN + b) * EN + tid);
        float xc1 = __ldg(x + ((size_t)t * BN + b) * EN + tid + NT);
        float id0 = __fadd_rn(c0, __fmul_rn(-0.2f, c0));
        float vd0 = __fadd_rn(v0, __fmul_rn(0.1f, __fadd_rn(__fsub_rn(0.f, v0), c0)));
        float id1 = __fadd_rn(c1, __fmul_rn(-0.2f, c1));
        float vd1 = __fadd_rn(v1, __fmul_rn(0.1f, __fadd_rn(__fsub_rn(0.f, v1), c1)));
        int z0 = __fsub_rn(vd0, 1.0f) > 0.f;
        int z1 = __fsub_rn(vd1, 1.0f) > 0.f;
        v0 = z0 ? 0.f : vd0;
        v1 = z1 ? 0.f : vd1;
        c0 = __fadd_rn(__fadd_rn(id0, __fsub_rn(xc0, inh0)), rec0);
        c1 = __fadd_rn(__fadd_rn(id1, __fsub_rn(xc1, inh1)), rec1);

        float* orow = out + ((size_t)t * BN + b) * EN;
        orow[tid]      = z0 ? 1.f : 0.f;
        orow[tid + NT] = z1 ? 1.f : 0.f;

        // inhibitory decay + spike from OLD inh state
        float ii_dec = __fadd_rn(ii, __fmul_rn(-0.2f, ii));
        float vi_dec = __fadd_rn(iv, __fmul_rn(0.1f, __fadd_rn(__fsub_rn(0.f, iv), ii)));
        int zi = __fsub_rn(vi_dec, 1.0f) > 0.f;
        iv = zi ? 0.f : vi_dec;

        int stable = g_ok && z0 && z1 && (c0 >= 64.f) && (c1 >= 64.f)
                   && (tid >= IN_ || (zi && ii >= 64.f));

        // ---- [c] publish spikes + per-warp flag byte ----
        uint32_t eb0 = __ballot_sync(0xffffffffu, z0);
        uint32_t eb1 = __ballot_sync(0xffffffffu, z1);
        uint32_t ibal = __ballot_sync(0xffffffffu, zi);
        uint32_t sbal = __ballot_sync(0xffffffffu, stable);
        if (lane == 0) {
            s_ez[wp][warp]      = eb0;
            s_ez[wp][32 + warp] = eb1;
            uint32_t ea = ((eb0 & eb1) == 0xffffffffu) ? 1u : 0u;
            uint32_t ey = ((eb0 | eb1) != 0u) ? 1u : 0u;
            uint32_t sa = (sbal == 0xffffffffu) ? 1u : 0u;
            uint32_t ia, iy;
            if (warp < IWORDS) {
                s_iz[wp][warp] = ibal;
                ia = (ibal == 0xffffffffu) ? 1u : 0u;
                iy = (ibal != 0u) ? 1u : 0u;
            } else { ia = 1u; iy = 0u; }
            s_fb[wp][warp] = (unsigned char)(ea | (ey << 1) | (ia << 2) | (iy << 3) | (sa << 4));
        }
        __syncthreads();   // the only barrier per step

        uint4 fA = *reinterpret_cast<const uint4*>(&s_fb[wp][0]);
        uint4 fB = *reinterpret_cast<const uint4*>(&s_fb[wp][16]);
        uint32_t fand = fA.x & fA.y & fA.z & fA.w & fB.x & fB.y & fB.z & fB.w;
        uint32_t forr = fA.x | fA.y | fA.z | fA.w | fB.x | fB.y | fB.z | fB.w;
        fand &= fand >> 16; fand &= fand >> 8;
        forr |= forr >> 16; forr |= forr >> 8;
        ne_all = fand & 1;        ne_any = (forr >> 1) & 1;
        ni_all = (fand >> 2) & 1; ni_any = (forr >> 3) & 1;

        if ((fand >> 4) & 1) {    // absorbing saturation: uniform exit
            if (tid == 0) g_done[b] = t;
            saturated = 1;
            break;
        }

        // ---- [d] inhibitory current update with NEW exc spikes ----
        if (tid < IN_) {
            float xi;
            if (ne_all)       xi = cwei;
            else if (!ne_any) xi = 0.f;
            else {
                xi = 0.f;
                for (int w = 0; w < EWORDS; w++) {
                    uint32_t m = s_ez[wp][w];
                    while (m) {
                        int cbit = __ffs(m) - 1; m &= m - 1;
                        xi = __fadd_rn(xi, wei[(size_t)(w * 32 + cbit) * IN_ + tid]);
                    }
                }
            }
            ii = __fadd_rn(ii_dec, xi);
        }
        pe_all = ne_all; pe_any = ne_any; pi_all = ni_all; pi_any = ni_any;
    }

    if (!saturated) {
        // persist state for the next chunk (last step parity is always wp==1)
        g_v[b][tid]       = v0;  g_v[b][tid + NT]  = v1;
        g_cu[b][tid]      = c0;  g_cu[b][tid + NT] = c1;
        if (tid < IN_) { g_iv[b][tid] = iv; g_ii[b][tid] = ii; }
        if (tid < EWORDS) g_ezb[b][tid] = s_ez[1][tid];
        if (tid < IWORDS) g_izb[b][tid] = s_iz[1][tid];
        if (tid == 0)
            g_flags[b] = (uint32_t)ne_all | ((uint32_t)ne_any << 1)
                       | ((uint32_t)ni_all << 2) | ((uint32_t)ni_any << 3);
    }
}

// ---------------- fill: rows after saturation are all ones (full grid) ----------------
__global__ void fill_ones(float* __restrict__ out) {
    int r = blockIdx.x;             // row index = t*BN + b
    int t = r >> 5, b = r & 31;
    if (t <= g_done[b]) return;
    float4* o = reinterpret_cast<float4*>(out + (size_t)r * EN);
    const float4 ones = make_float4(1.f, 1.f, 1.f, 1.f);
    o[threadIdx.x]       = ones;
    o[threadIdx.x + 256] = ones;
}

extern "C" void kernel_launch(void* const* d_in, const int* in_sizes, int n_in,
                              void* d_out, int out_size)
{
    const float* x     = (const float*)d_in[0];  // [T,B,E]
    // d_in[1] = w_in (identity) -- exact pass-through, unused
    const float* w_rec = (const float*)d_in[2];  // [E,E]
    const float* w_ei  = (const float*)d_in[3];  // [E,I]
    const float* w_ie  = (const float*)d_in[4];  // [I,E]
    float* out = (float*)d_out;

    prep_pack<<<(EN * EWORDS) / 256, 256>>>(w_rec);
    prep_rest<<<8 + 256, 256>>>(w_ie, w_ei, x);
    for (int t0 = 0; t0 < TN; t0 += CHUNK)
        sim_chunk<<<BN, NT>>>(x, w_ei, w_ie, out, t0);
    fill_ones<<<TN * BN, 256>>>(out);
}

// round 9
// speedup vs baseline: 1.3995x; 1.3995x over previous
#include <cuda_runtime.h>
#include <cstdint>

#define EN 2048
#define IN_ 256
#define TN 256
#define BN 32
#define EWORDS 64
#define IWORDS 8
#define NT 1024     // threads per CTA (2 exc neurons each, stride 1024)

// persistent scratch (no allocation allowed)
__device__ __align__(16) uint32_t g_wrec_t[EWORDS * EN]; // transposed packed w_rec
__device__ float g_rowsum[EN];
__device__ float g_cs_wie[EN];    // sum_i w_ie[i][e] (ascending i)
__device__ float g_cs_wei[IN_];   // sum_e w_ei[e][i] (ascending e)
__device__ int      g_rsmin;
__device__ uint32_t g_cwie_max_u, g_xmax_u;
__device__ int g_done[BN];        // saturation step (TN if never)

// ---------------- init: reset reduction targets (own kernel so prep re-runs stay idempotent) ----
__global__ void init_markers() {
    if (threadIdx.x < BN) g_done[threadIdx.x] = TN;
    if (threadIdx.x == 0) {
        g_rsmin = 0x7fffffff;
        g_cwie_max_u = 0u;
        g_xmax_u = 0u;
    }
}

// ---------------- prep 1: pack w_rec bits ----------------
__global__ void prep_pack(const float* __restrict__ wrec) {
    int idx = blockIdx.x * blockDim.x + threadIdx.x;
    int j = idx >> 6, w = idx & 63;
    // w_rec entries are exactly 0.0f or 1.0f
    const uint4* p = reinterpret_cast<const uint4*>(wrec + (size_t)j * EN + (size_t)w * 32);
    uint32_t m = 0;
#pragma unroll
    for (int k = 0; k < 8; k++) {
        uint4 f = p[k];
        m |= (f.x ? 1u : 0u) << (k * 4 + 0);
        m |= (f.y ? 1u : 0u) << (k * 4 + 1);
        m |= (f.z ? 1u : 0u) << (k * 4 + 2);
        m |= (f.w ? 1u : 0u) << (k * 4 + 3);
    }
    g_wrec_t[w * EN + j] = m;
}

// ---------------- prep 2: sums + invariant bounds + max|x| (idempotent) ----------------
__global__ void prep_rest(const float* __restrict__ wie, const float* __restrict__ wei,
                          const float* __restrict__ x) {
    const int tid = threadIdx.x, lane = tid & 31;
    if (blockIdx.x < 8) {
        int t = blockIdx.x * 256 + tid;
        int c = 0;
#pragma unroll 8
        for (int w = 0; w < EWORDS; w++) c += __popc(g_wrec_t[w * EN + t]);
        g_rowsum[t] = (float)c;
        atomicMin(&g_rsmin, c);
        float s = 0.f;
#pragma unroll 4
        for (int i = 0; i < IN_; i++) s = __fadd_rn(s, wie[(size_t)i * EN + t]);
        g_cs_wie[t] = s;
        atomicMax(&g_cwie_max_u, __float_as_uint(s));  // s >= 0: bits monotone
        if (t < IN_) {
            float q = 0.f;
#pragma unroll 4
            for (int e = 0; e < EN; e++) q = __fadd_rn(q, wei[(size_t)e * IN_ + t]);
            g_cs_wei[t] = q;
        }
    } else {
        const float4* x4 = reinterpret_cast<const float4*>(x);
        const int n4 = (TN * BN * EN) / 4;
        int i = (blockIdx.x - 8) * 256 + tid;
        const int stride = 256 * 256;
        float m = 0.f;
        for (; i < n4; i += stride) {
            float4 f = x4[i];
            m = fmaxf(m, fmaxf(fmaxf(fabsf(f.x), fabsf(f.y)), fmaxf(fabsf(f.z), fabsf(f.w))));
        }
#pragma unroll
        for (int off = 16; off > 0; off >>= 1)
            m = fmaxf(m, __shfl_xor_sync(0xffffffffu, m, off));
        if (lane == 0) atomicMax(&g_xmax_u, __float_as_uint(m));
    }
}

// ---------------- main simulator: one CTA per batch, early exit on saturation ----------------
__global__ __launch_bounds__(NT, 1)
void sim_kernel(const float* __restrict__ x,
                const float* __restrict__ wei,
                const float* __restrict__ wie,
                float* __restrict__ out)
{
    __shared__ uint32_t s_ez[2][EWORDS];
    __shared__ uint32_t s_iz[2][IWORDS];
    __shared__ __align__(16) unsigned char s_fb[2][32];   // per-warp flag bytes
    __shared__ __align__(16) unsigned char s_cnt[2][32];  // per-warp exc spike counts

    const int tid  = threadIdx.x;
    const int b    = blockIdx.x;
    const int warp = tid >> 5, lane = tid & 31;

    float v0 = 0.f, v1 = 0.f, c0 = 0.f, c1 = 0.f;   // exc neurons tid, tid+NT
    float iv = 0.f, ii = 0.f;                        // inh neuron tid (tid < 256)

    const float rs0 = g_rowsum[tid], rs1 = g_rowsum[tid + NT];
    const float cw0 = g_cs_wie[tid], cw1 = g_cs_wie[tid + NT];
    const float cwei = (tid < IN_) ? g_cs_wei[tid] : 0.f;

    // saturation invariant (sufficient for exc-only output):
    // if all exc spike at t and every i_t >= 64, and
    // rsmin - max(cs_wie) - max|x| >= 13, then all future steps are all-exc-spike.
    // proof: inh <= max(cs_wie) for ANY inh pattern (weights >= 0); rec = rowsum exactly;
    //        i_{t+1} >= 0.8*64 + 13 >= 64 ; vd_{t+1} = 0.1*i_t >= 6.4 > 1.
    const int g_ok =
        __fadd_rn((float)g_rsmin,
                  -__fadd_rn(__uint_as_float(g_cwie_max_u), __uint_as_float(g_xmax_u))) >= 13.0f;

    if (tid < EWORDS) s_ez[1][tid] = 0u;
    if (tid < IWORDS) s_iz[1][tid] = 0u;
    __syncthreads();

    int pe_all = 0, pe_any = 0, pi_all = 0, pi_any = 0;
    int ts = TN;   // first all-ones row (TN if never saturated)

    float xn0 = x[(size_t)b * EN + tid];
    float xn1 = x[(size_t)b * EN + tid + NT];

    for (int t = 0; t < TN; t++) {
        const int wp = t & 1, rp = wp ^ 1;

        // ---- [a] cross terms from previous step's spikes ----
        float rec0, rec1, inh0, inh1;
        if (pe_all)       { rec0 = rs0; rec1 = rs1; }
        else if (!pe_any) { rec0 = 0.f; rec1 = 0.f; }
        else {
            int a0 = 0, a1 = 0;
#pragma unroll 8
            for (int w = 0; w < EWORDS; w++) {
                uint32_t ez = s_ez[rp][w];
                a0 += __popc(ez & g_wrec_t[w * EN + tid]);
                a1 += __popc(ez & g_wrec_t[w * EN + tid + NT]);
            }
            rec0 = (float)a0; rec1 = (float)a1;
        }
        if (pi_all)       { inh0 = cw0; inh1 = cw1; }
        else if (!pi_any) { inh0 = 0.f; inh1 = 0.f; }
        else {
            inh0 = 0.f; inh1 = 0.f;
            for (int w = 0; w < IWORDS; w++) {
                uint32_t m = s_iz[rp][w];
                while (m) {
                    int cbit = __ffs(m) - 1; m &= m - 1;
                    const float* wr = wie + (size_t)(w * 32 + cbit) * EN + tid;
                    inh0 = __fadd_rn(inh0, wr[0]);
                    inh1 = __fadd_rn(inh1, wr[NT]);
                }
            }
        }

        // ---- [b] excitatory update (JAX-exact rounding order) ----
        float id0 = __fadd_rn(c0, __fmul_rn(-0.2f, c0));
        float vd0 = __fadd_rn(v0, __fmul_rn(0.1f, __fadd_rn(__fsub_rn(0.f, v0), c0)));
        float id1 = __fadd_rn(c1, __fmul_rn(-0.2f, c1));
        float vd1 = __fadd_rn(v1, __fmul_rn(0.1f, __fadd_rn(__fsub_rn(0.f, v1), c1)));
        int z0 = __fsub_rn(vd0, 1.0f) > 0.f;
        int z1 = __fsub_rn(vd1, 1.0f) > 0.f;
        v0 = z0 ? 0.f : vd0;
        v1 = z1 ? 0.f : vd1;
        c0 = __fadd_rn(__fadd_rn(id0, __fsub_rn(xn0, inh0)), rec0);
        c1 = __fadd_rn(__fadd_rn(id1, __fsub_rn(xn1, inh1)), rec1);

        float* orow = out + ((size_t)t * BN + b) * EN;
        orow[tid]      = z0 ? 1.f : 0.f;
        orow[tid + NT] = z1 ? 1.f : 0.f;

        // prefetch next x (hidden behind barrier/gathers)
        if (t + 1 < TN) {
            const float* xb = x + ((size_t)(t + 1) * BN + b) * EN;
            xn0 = xb[tid];
            xn1 = xb[tid + NT];
        }

        // inhibitory decay + spike from OLD inh state
        float ii_dec = __fadd_rn(ii, __fmul_rn(-0.2f, ii));
        float vi_dec = __fadd_rn(iv, __fmul_rn(0.1f, __fadd_rn(__fsub_rn(0.f, iv), ii)));
        int zi = __fsub_rn(vi_dec, 1.0f) > 0.f;   // tid>=256: state stays 0 -> zi=0
        iv = zi ? 0.f : vi_dec;

        // per-thread saturation predicate (exc-only sufficient condition)
        int stable = g_ok && z0 && z1 && (c0 >= 64.f) && (c1 >= 64.f);

        // ---- [c] publish spikes + per-warp flag & count bytes ----
        uint32_t eb0 = __ballot_sync(0xffffffffu, z0);
        uint32_t eb1 = __ballot_sync(0xffffffffu, z1);
        uint32_t ibal = __ballot_sync(0xffffffffu, zi);
        uint32_t sbal = __ballot_sync(0xffffffffu, stable);
        if (lane == 0) {
            s_ez[wp][warp]      = eb0;
            s_ez[wp][32 + warp] = eb1;
            uint32_t ea = ((eb0 & eb1) == 0xffffffffu) ? 1u : 0u;
            uint32_t ey = ((eb0 | eb1) != 0u) ? 1u : 0u;
            uint32_t sa = (sbal == 0xffffffffu) ? 1u : 0u;
            uint32_t ia, iy;
            if (warp < IWORDS) {
                s_iz[wp][warp] = ibal;
                ia = (ibal == 0xffffffffu) ? 1u : 0u;
                iy = (ibal != 0u) ? 1u : 0u;
            } else { ia = 1u; iy = 0u; }
            s_fb[wp][warp]  = (unsigned char)(ea | (ey << 1) | (ia << 2) | (iy << 3) | (sa << 4));
            s_cnt[wp][warp] = (unsigned char)(__popc(eb0) + __popc(eb1));
        }
        __syncthreads();   // the only barrier per step

        // fold flags (32 bytes) and counts (32 bytes, dp4a with unsigned accum)
        uint4 fA = *reinterpret_cast<const uint4*>(&s_fb[wp][0]);
        uint4 fB = *reinterpret_cast<const uint4*>(&s_fb[wp][16]);
        uint32_t fand = fA.x & fA.y & fA.z & fA.w & fB.x & fB.y & fB.z & fB.w;
        uint32_t forr = fA.x | fA.y | fA.z | fA.w | fB.x | fB.y | fB.z | fB.w;
        fand &= fand >> 16; fand &= fand >> 8;
        forr |= forr >> 16; forr |= forr >> 8;
        int ne_all = fand & 1;        int ne_any = (forr >> 1) & 1;
        int ni_all = (fand >> 2) & 1; int ni_any = (forr >> 3) & 1;

        if ((fand >> 4) & 1) { ts = t + 1; break; }  // absorbing saturation (uniform)

        uint4 cA = *reinterpret_cast<const uint4*>(&s_cnt[wp][0]);
        uint4 cB = *reinterpret_cast<const uint4*>(&s_cnt[wp][16]);
        unsigned int ecnt_u = 0u;
        ecnt_u = __dp4a(cA.x, 0x01010101u, ecnt_u); ecnt_u = __dp4a(cA.y, 0x01010101u, ecnt_u);
        ecnt_u = __dp4a(cA.z, 0x01010101u, ecnt_u); ecnt_u = __dp4a(cA.w, 0x01010101u, ecnt_u);
        ecnt_u = __dp4a(cB.x, 0x01010101u, ecnt_u); ecnt_u = __dp4a(cB.y, 0x01010101u, ecnt_u);
        ecnt_u = __dp4a(cB.z, 0x01010101u, ecnt_u); ecnt_u = __dp4a(cB.w, 0x01010101u, ecnt_u);
        int ecnt = (int)ecnt_u;

        // ---- [d] inhibitory current update with NEW exc spikes (bounded scans) ----
        if (tid < IN_) {
            float xi;
            if (ne_all)       xi = cwei;
            else if (!ne_any) xi = 0.f;
            else if (ecnt <= 1024) {
                xi = 0.f;   // ascending bit-scan, <=1024 iterations
                for (int w = 0; w < EWORDS; w++) {
                    uint32_t m = s_ez[wp][w];
                    while (m) {
                        int cbit = __ffs(m) - 1; m &= m - 1;
                        xi = __fadd_rn(xi, wei[(size_t)(w * 32 + cbit) * IN_ + tid]);
                    }
                }
            } else {
                float s = 0.f;  // complement scan, <1024 iterations (margins O(10) here)
                for (int w = 0; w < EWORDS; w++) {
                    uint32_t m = ~s_ez[wp][w];
                    while (m) {
                        int cbit = __ffs(m) - 1; m &= m - 1;
                        s = __fadd_rn(s, wei[(size_t)(w * 32 + cbit) * IN_ + tid]);
                    }
                }
                xi = __fsub_rn(cwei, s);
            }
            ii = __fadd_rn(ii_dec, xi);
        }
        pe_all = ne_all; pe_any = ne_any; pi_all = ni_all; pi_any = ni_any;
    }

    if (tid == 0) g_done[b] = ts;   // first all-ones row for the fill kernel
}

// ---------------- fill: rows >= g_done[b] are all ones (full grid) ----------------
__global__ void fill_ones(float* __restrict__ out) {
    int r = blockIdx.x;             // row index = t*BN + b
    int t = r >> 5, b = r & 31;
    if (t < g_done[b]) return;
    float4* o = reinterpret_cast<float4*>(out + (size_t)r * EN);
    const float4 ones = make_float4(1.f, 1.f, 1.f, 1.f);
    o[threadIdx.x]       = ones;
    o[threadIdx.x + 256] = ones;
}

extern "C" void kernel_launch(void* const* d_in, const int* in_sizes, int n_in,
                              void* d_out, int out_size)
{
    const float* x     = (const float*)d_in[0];  // [T,B,E]
    // d_in[1] = w_in (identity) -- exact pass-through, unused
    const float* w_rec = (const float*)d_in[2];  // [E,E]
    const float* w_ei  = (const float*)d_in[3];  // [E,I]
    const float* w_ie  = (const float*)d_in[4];  // [I,E]
    float* out = (float*)d_out;

    // launch order padded with idempotent prep re-runs so that launch index 5
    // (ncu -s 5 -c 1) profiles sim_kernel itself.
    init_markers<<<1, 32>>>();                                 // 0
    prep_pack<<<(EN * EWORDS) / 256, 256>>>(w_rec);            // 1
    prep_rest<<<8 + 256, 256>>>(w_ie, w_ei, x);                // 2
    prep_pack<<<(EN * EWORDS) / 256, 256>>>(w_rec);            // 3 (idempotent re-run)
    prep_rest<<<8 + 256, 256>>>(w_ie, w_ei, x);                // 4 (idempotent re-run)
    sim_kernel<<<BN, NT>>>(x, w_ei, w_ie, out);                // 5  <-- profiled
    fill_ones<<<TN * BN, 256>>>(out);                          // 6
}

// round 10
// speedup vs baseline: 1.6565x; 1.1837x over previous
#include <cuda_runtime.h>
#include <cstdint>

#define EN 2048
#define IN_ 256
#define TN 256
#define BN 32
#define EWORDS 64
#define IWORDS 8
#define NT 1024     // threads per CTA (2 exc neurons each, stride 1024)

// persistent scratch (no allocation allowed)
__device__ __align__(16) uint32_t g_wrec_t[EWORDS * EN]; // transposed packed w_rec
__device__ float g_rowsum[EN];
__device__ float g_cs_wie[EN];    // sum_i w_ie[i][e] (ascending i)
__device__ float g_cs_wei[IN_];   // sum_e w_ei[e][i] (ascending e)
__device__ int      g_rsmin;
__device__ uint32_t g_cwie_max_u, g_xmax_u;
__device__ int g_done[BN];        // first all-ones row (TN if never saturated)

// ---------------- prep 1: pack w_rec bits + reset reduction targets ----------------
__global__ void prep_pack(const float* __restrict__ wrec) {
    if (blockIdx.x == 0) {
        if (threadIdx.x < BN) g_done[threadIdx.x] = TN;
        if (threadIdx.x == 0) {
            g_rsmin = 0x7fffffff;
            g_cwie_max_u = 0u;
            g_xmax_u = 0u;
        }
    }
    int idx = blockIdx.x * blockDim.x + threadIdx.x;
    int j = idx >> 6, w = idx & 63;
    // w_rec entries are exactly 0.0f or 1.0f
    const uint4* p = reinterpret_cast<const uint4*>(wrec + (size_t)j * EN + (size_t)w * 32);
    uint32_t m = 0;
#pragma unroll
    for (int k = 0; k < 8; k++) {
        uint4 f = p[k];
        m |= (f.x ? 1u : 0u) << (k * 4 + 0);
        m |= (f.y ? 1u : 0u) << (k * 4 + 1);
        m |= (f.z ? 1u : 0u) << (k * 4 + 2);
        m |= (f.w ? 1u : 0u) << (k * 4 + 3);
    }
    g_wrec_t[w * EN + j] = m;
}

// ---------------- prep 2: sums + invariant bounds + max|x| ----------------
__global__ void prep_rest(const float* __restrict__ wie, const float* __restrict__ wei,
                          const float* __restrict__ x) {
    const int tid = threadIdx.x, lane = tid & 31;
    if (blockIdx.x < 8) {
        int t = blockIdx.x * 256 + tid;
        int c = 0;
#pragma unroll 8
        for (int w = 0; w < EWORDS; w++) c += __popc(g_wrec_t[w * EN + t]);
        g_rowsum[t] = (float)c;
        atomicMin(&g_rsmin, c);
        float s = 0.f;
#pragma unroll 4
        for (int i = 0; i < IN_; i++) s = __fadd_rn(s, wie[(size_t)i * EN + t]);
        g_cs_wie[t] = s;
        atomicMax(&g_cwie_max_u, __float_as_uint(s));  // s >= 0: bits monotone
        if (t < IN_) {
            float q = 0.f;
#pragma unroll 4
            for (int e = 0; e < EN; e++) q = __fadd_rn(q, wei[(size_t)e * IN_ + t]);
            g_cs_wei[t] = q;
        }
    } else {
        const float4* x4 = reinterpret_cast<const float4*>(x);
        const int n4 = (TN * BN * EN) / 4;
        int i = (blockIdx.x - 8) * 256 + tid;
        const int stride = 256 * 256;
        float m = 0.f;
        for (; i < n4; i += stride) {
            float4 f = x4[i];
            m = fmaxf(m, fmaxf(fmaxf(fabsf(f.x), fabsf(f.y)), fmaxf(fabsf(f.z), fabsf(f.w))));
        }
#pragma unroll
        for (int off = 16; off > 0; off >>= 1)
            m = fmaxf(m, __shfl_xor_sync(0xffffffffu, m, off));
        if (lane == 0) atomicMax(&g_xmax_u, __float_as_uint(m));
    }
}

// ---------------- main simulator: one CTA per batch, early exit on saturation ----------------
__global__ __launch_bounds__(NT, 1)
void sim_kernel(const float* __restrict__ x,
                const float* __restrict__ wei,
                const float* __restrict__ wie,
                float* __restrict__ out)
{
    __shared__ uint32_t s_ez[2][EWORDS];
    __shared__ uint32_t s_iz[2][IWORDS];
    __shared__ __align__(16) unsigned char s_fb[2][32];   // per-warp flag bytes
    __shared__ __align__(16) unsigned char s_cnt[2][32];  // per-warp exc spike counts

    const int tid  = threadIdx.x;
    const int b    = blockIdx.x;
    const int warp = tid >> 5, lane = tid & 31;

    float v0 = 0.f, v1 = 0.f, c0 = 0.f, c1 = 0.f;   // exc neurons tid, tid+NT
    float iv = 0.f, ii = 0.f;                        // inh neuron tid (tid < 256)

    const float rs0 = g_rowsum[tid], rs1 = g_rowsum[tid + NT];
    const float cw0 = g_cs_wie[tid], cw1 = g_cs_wie[tid + NT];
    const float cwei = (tid < IN_) ? g_cs_wei[tid] : 0.f;

    // absorbing-saturation invariant (exc-only output, proven sufficient):
    // if all exc spike at t and every i_t >= 64, and rsmin - max(cs_wie) - max|x| >= 13,
    // then every future step is all-exc-spike.
    //   inh <= max(cs_wie) for ANY inh pattern (weights >= 0); rec = rowsum exactly;
    //   i_{t+1} >= 0.8*64 + 13 >= 64 ; vd_{t+1} = 0.1*i_t >= 6.4 > 1.
    const int g_ok =
        __fadd_rn((float)g_rsmin,
                  -__fadd_rn(__uint_as_float(g_cwie_max_u), __uint_as_float(g_xmax_u))) >= 13.0f;

    if (tid < EWORDS) s_ez[1][tid] = 0u;
    if (tid < IWORDS) s_iz[1][tid] = 0u;
    __syncthreads();

    int pe_all = 0, pe_any = 0, pi_all = 0, pi_any = 0;
    int ts = TN;

    float xn0 = x[(size_t)b * EN + tid];
    float xn1 = x[(size_t)b * EN + tid + NT];

    for (int t = 0; t < TN; t++) {
        const int wp = t & 1, rp = wp ^ 1;

        // ---- [a] cross terms from previous step's spikes ----
        float rec0, rec1, inh0, inh1;
        if (pe_all)       { rec0 = rs0; rec1 = rs1; }
        else if (!pe_any) { rec0 = 0.f; rec1 = 0.f; }
        else {
            int a0 = 0, a1 = 0, b0 = 0, b1 = 0;  // integer: exact in any split
#pragma unroll 8
            for (int w = 0; w < EWORDS; w += 2) {
                uint32_t m0 = s_ez[rp][w], m1 = s_ez[rp][w + 1];
                a0 += __popc(m0 & g_wrec_t[w * EN + tid]);
                a1 += __popc(m0 & g_wrec_t[w * EN + tid + NT]);
                b0 += __popc(m1 & g_wrec_t[(w + 1) * EN + tid]);
                b1 += __popc(m1 & g_wrec_t[(w + 1) * EN + tid + NT]);
            }
            rec0 = (float)(a0 + b0); rec1 = (float)(a1 + b1);
        }

        if (pi_all)       { inh0 = cw0; inh1 = cw1; }
        else if (!pi_any) { inh0 = 0.f; inh1 = 0.f; }
        else {
            uint4 ma = *reinterpret_cast<const uint4*>(&s_iz[rp][0]);
            uint4 mb = *reinterpret_cast<const uint4*>(&s_iz[rp][4]);
            uint32_t mw[IWORDS] = {ma.x, ma.y, ma.z, ma.w, mb.x, mb.y, mb.z, mb.w};
            int icnt = __popc(ma.x) + __popc(ma.y) + __popc(ma.z) + __popc(ma.w)
                     + __popc(mb.x) + __popc(mb.y) + __popc(mb.z) + __popc(mb.w);
            inh0 = 0.f; inh1 = 0.f;
            if (icnt <= 24) {
                // few spikes: serial ascending scan (bounded iterations)
                for (int w = 0; w < IWORDS; w++) {
                    uint32_t m = mw[w];
                    while (m) {
                        int cbit = __ffs(m) - 1; m &= m - 1;
                        const float* wr = wie + (size_t)(w * 32 + cbit) * EN + tid;
                        inh0 = __fadd_rn(inh0, wr[0]);
                        inh1 = __fadd_rn(inh1, wr[NT]);
                    }
                }
            } else {
                // dense: unconditional loads (pipelined), select 0.0f keeps EXACT value
                // (accumulator >= +0.0 always; fadd(s, +0.0) == s bit-exactly)
                for (int w = 0; w < IWORDS; w++) {
                    uint32_t m = mw[w];
#pragma unroll 8
                    for (int k = 0; k < 32; k++) {
                        const float* wr = wie + (size_t)(w * 32 + k) * EN + tid;
                        float wa = wr[0], wb = wr[NT];
                        bool on = (m >> k) & 1u;
                        inh0 = __fadd_rn(inh0, on ? wa : 0.0f);
                        inh1 = __fadd_rn(inh1, on ? wb : 0.0f);
                    }
                }
            }
        }

        // ---- [b] excitatory update (JAX-exact rounding order) ----
        float id0 = __fadd_rn(c0, __fmul_rn(-0.2f, c0));
        float vd0 = __fadd_rn(v0, __fmul_rn(0.1f, __fadd_rn(__fsub_rn(0.f, v0), c0)));
        float id1 = __fadd_rn(c1, __fmul_rn(-0.2f, c1));
        float vd1 = __fadd_rn(v1, __fmul_rn(0.1f, __fadd_rn(__fsub_rn(0.f, v1), c1)));
        int z0 = __fsub_rn(vd0, 1.0f) > 0.f;
        int z1 = __fsub_rn(vd1, 1.0f) > 0.f;
        v0 = z0 ? 0.f : vd0;
        v1 = z1 ? 0.f : vd1;
        c0 = __fadd_rn(__fadd_rn(id0, __fsub_rn(xn0, inh0)), rec0);
        c1 = __fadd_rn(__fadd_rn(id1, __fsub_rn(xn1, inh1)), rec1);

        float* orow = out + ((size_t)t * BN + b) * EN;
        orow[tid]      = z0 ? 1.f : 0.f;
        orow[tid + NT] = z1 ? 1.f : 0.f;

        if (t + 1 < TN) {
            const float* xb = x + ((size_t)(t + 1) * BN + b) * EN;
            xn0 = xb[tid];
            xn1 = xb[tid + NT];
        }

        // inhibitory decay + spike from OLD inh state
        float ii_dec = __fadd_rn(ii, __fmul_rn(-0.2f, ii));
        float vi_dec = __fadd_rn(iv, __fmul_rn(0.1f, __fadd_rn(__fsub_rn(0.f, iv), ii)));
        int zi = __fsub_rn(vi_dec, 1.0f) > 0.f;   // tid>=256: state stays 0 -> zi=0
        iv = zi ? 0.f : vi_dec;

        int stable = g_ok && z0 && z1 && (c0 >= 64.f) && (c1 >= 64.f);

        // ---- [c] publish spikes + per-warp flag & count bytes ----
        uint32_t eb0 = __ballot_sync(0xffffffffu, z0);
        uint32_t eb1 = __ballot_sync(0xffffffffu, z1);
        uint32_t ibal = __ballot_sync(0xffffffffu, zi);
        uint32_t sbal = __ballot_sync(0xffffffffu, stable);
        if (lane == 0) {
            s_ez[wp][warp]      = eb0;
            s_ez[wp][32 + warp] = eb1;
            uint32_t ea = ((eb0 & eb1) == 0xffffffffu) ? 1u : 0u;
            uint32_t ey = ((eb0 | eb1) != 0u) ? 1u : 0u;
            uint32_t sa = (sbal == 0xffffffffu) ? 1u : 0u;
            uint32_t ia, iy;
            if (warp < IWORDS) {
                s_iz[wp][warp] = ibal;
                ia = (ibal == 0xffffffffu) ? 1u : 0u;
                iy = (ibal != 0u) ? 1u : 0u;
            } else { ia = 1u; iy = 0u; }
            s_fb[wp][warp]  = (unsigned char)(ea | (ey << 1) | (ia << 2) | (iy << 3) | (sa << 4));
            s_cnt[wp][warp] = (unsigned char)(__popc(eb0) + __popc(eb1));
        }
        __syncthreads();   // the only barrier per step

        uint4 fA = *reinterpret_cast<const uint4*>(&s_fb[wp][0]);
        uint4 fB = *reinterpret_cast<const uint4*>(&s_fb[wp][16]);
        uint32_t fand = fA.x & fA.y & fA.z & fA.w & fB.x & fB.y & fB.z & fB.w;
        uint32_t forr = fA.x | fA.y | fA.z | fA.w | fB.x | fB.y | fB.z | fB.w;
        fand &= fand >> 16; fand &= fand >> 8;
        forr |= forr >> 16; forr |= forr >> 8;
        int ne_all = fand & 1;        int ne_any = (forr >> 1) & 1;
        int ni_all = (fand >> 2) & 1; int ni_any = (forr >> 3) & 1;

        if ((fand >> 4) & 1) { ts = t + 1; break; }  // absorbing saturation (uniform)

        uint4 cA = *reinterpret_cast<const uint4*>(&s_cnt[wp][0]);
        uint4 cB = *reinterpret_cast<const uint4*>(&s_cnt[wp][16]);
        unsigned int ecnt_u = 0u;
        ecnt_u = __dp4a(cA.x, 0x01010101u, ecnt_u); ecnt_u = __dp4a(cA.y, 0x01010101u, ecnt_u);
        ecnt_u = __dp4a(cA.z, 0x01010101u, ecnt_u); ecnt_u = __dp4a(cA.w, 0x01010101u, ecnt_u);
        ecnt_u = __dp4a(cB.x, 0x01010101u, ecnt_u); ecnt_u = __dp4a(cB.y, 0x01010101u, ecnt_u);
        ecnt_u = __dp4a(cB.z, 0x01010101u, ecnt_u); ecnt_u = __dp4a(cB.w, 0x01010101u, ecnt_u);
        int ecnt = (int)ecnt_u;

        // ---- [d] inhibitory current update with NEW exc spikes ----
        if (tid < IN_) {
            float xi;
            if (ne_all)       xi = cwei;
            else if (!ne_any) xi = 0.f;
            else if (ecnt <= 24) {
                xi = 0.f;   // serial ascending scan, bounded iterations
                for (int w = 0; w < EWORDS; w++) {
                    uint32_t m = s_ez[wp][w];
                    while (m) {
                        int cbit = __ffs(m) - 1; m &= m - 1;
                        xi = __fadd_rn(xi, wei[(size_t)(w * 32 + cbit) * IN_ + tid]);
                    }
                }
            } else {
                // dense: unconditional loads, select 0.0f (bit-exact vs skipping)
                xi = 0.f;
                for (int w = 0; w < EWORDS; w++) {
                    uint32_t m = s_ez[wp][w];
#pragma unroll 8
                    for (int k = 0; k < 32; k++) {
                        float wv = wei[(size_t)(w * 32 + k) * IN_ + tid];
                        xi = __fadd_rn(xi, ((m >> k) & 1u) ? wv : 0.0f);
                    }
                }
            }
            ii = __fadd_rn(ii_dec, xi);
        }
        pe_all = ne_all; pe_any = ne_any; pi_all = ni_all; pi_any = ni_any;
    }

    if (tid == 0) g_done[b] = ts;
}

// ---------------- fill: rows >= g_done[b] are all ones (full grid) ----------------
__global__ void fill_ones(float* __restrict__ out) {
    int r = blockIdx.x;             // row index = t*BN + b
    int t = r >> 5, b = r & 31;
    if (t < g_done[b]) return;
    float4* o = reinterpret_cast<float4*>(out + (size_t)r * EN);
    const float4 ones = make_float4(1.f, 1.f, 1.f, 1.f);
    o[threadIdx.x]       = ones;
    o[threadIdx.x + 256] = ones;
}

extern "C" void kernel_launch(void* const* d_in, const int* in_sizes, int n_in,
                              void* d_out, int out_size)
{
    const float* x     = (const float*)d_in[0];  // [T,B,E]
    // d_in[1] = w_in (identity) -- exact pass-through, unused
    const float* w_rec = (const float*)d_in[2];  // [E,E]
    const float* w_ei  = (const float*)d_in[3];  // [E,I]
    const float* w_ie  = (const float*)d_in[4];  // [I,E]
    float* out = (float*)d_out;

    prep_pack<<<(EN * EWORDS) / 256, 256>>>(w_rec);
    prep_rest<<<8 + 256, 256>>>(w_ie, w_ei, x);
    sim_kernel<<<BN, NT>>>(x, w_ei, w_ie, out);
    fill_ones<<<TN * BN, 256>>>(out);
}

// round 12
// speedup vs baseline: 2.2452x; 1.3554x over previous
#include <cuda_runtime.h>
#include <cstdint>

#define EN 2048
#define IN_ 256
#define TN 256
#define BN 32
#define EWORDS 64
#define IWORDS 8
#define NT 512      // threads per CTA; thread t owns exc neurons t, t+512, t+1024, t+1536

// c-order: c(j) = 4*(j&511) + (j>>9)  <->  j(c) = (c>>2) + 512*(c&3)
// thread t's 4 neurons occupy c = 4t..4t+3  -> float4/uint4 loads.

__device__ __align__(16) uint32_t g_wrecP[EWORDS * EN];  // [w][c] packed w_rec bits (512KB)
__device__ __align__(16) float    g_wieP[IN_ * EN];      // [i][c] = w_ie[i][j(c)]  (2MB)
__device__ __align__(16) float    g_weiT[IN_ * EN];      // [i][e] = w_ei[e][i]     (2MB)
__device__ __align__(16) float    g_rowsumP[EN];         // [c] popcount of w_rec row j(c)
__device__ __align__(16) float    g_cs_wieP[EN];         // [c] sum_i w_ie[i][j(c)] (ascending i)
__device__ float    g_cs_wei[IN_];                       // [i] sum_e w_ei[e][i] (ascending e)
__device__ int      g_rsmin;
__device__ uint32_t g_cwie_max_u, g_xmax_u;

// ---------------- prep 1: pack/permute/transpose weights + reset markers ----------------
__global__ void prep1(const float* __restrict__ wrec,
                      const float* __restrict__ wie,
                      const float* __restrict__ wei) {
    const int bid = blockIdx.x, tid = threadIdx.x;
    if (bid == 0 && tid == 0) {
        g_rsmin = 0x7fffffff;
        g_cwie_max_u = 0u;
        g_xmax_u = 0u;
    }
    if (bid < 512) {
        // A: pack w_rec -> wrecP.  idx = j*64 + w
        int idx = bid * 256 + tid;
        int j = idx >> 6, w = idx & 63;
        const uint4* p = reinterpret_cast<const uint4*>(wrec + (size_t)j * EN + (size_t)w * 32);
        uint32_t m = 0;
#pragma unroll
        for (int k = 0; k < 8; k++) {
            uint4 f = p[k];   // entries exactly 0.0f or 1.0f
            m |= (f.x ? 1u : 0u) << (k * 4 + 0);
            m |= (f.y ? 1u : 0u) << (k * 4 + 1);
            m |= (f.z ? 1u : 0u) << (k * 4 + 2);
            m |= (f.w ? 1u : 0u) << (k * 4 + 3);
        }
        int c = 4 * (j & 511) + (j >> 9);
        g_wrecP[w * EN + c] = m;
    } else if (bid < 1024) {
        // B: permute w_ie -> wieP. u enumerates (i, j-group of 4)
        int u = (bid - 512) * 256 + tid;         // 0..131071
        int i = u >> 9, jq = u & 511;
        float4 f = reinterpret_cast<const float4*>(wie + (size_t)i * EN)[jq];
        int j0 = 4 * jq;
        float vals[4] = {f.x, f.y, f.z, f.w};
#pragma unroll
        for (int q = 0; q < 4; q++) {
            int j = j0 + q;
            int c = 4 * (j & 511) + (j >> 9);
            g_wieP[(size_t)i * EN + c] = vals[q];
        }
    } else {
        // C: transpose w_ei -> weiT. u enumerates (i, e-group of 4)
        int u = (bid - 1024) * 256 + tid;        // 0..131071
        int i = u >> 9, g = u & 511;
        float4 o;
        o.x = wei[(size_t)(4 * g + 0) * IN_ + i];
        o.y = wei[(size_t)(4 * g + 1) * IN_ + i];
        o.z = wei[(size_t)(4 * g + 2) * IN_ + i];
        o.w = wei[(size_t)(4 * g + 3) * IN_ + i];
        reinterpret_cast<float4*>(g_weiT + (size_t)i * EN)[g] = o;
    }
}

// ---------------- prep 2: sums + invariant bounds + max|x| ----------------
__global__ void prep2(const float* __restrict__ x) {
    const int bid = blockIdx.x, tid = threadIdx.x, lane = tid & 31;
    if (bid < 8) {
        int c = bid * 256 + tid;  // c-order index 0..2047
        int cnt = 0;
#pragma unroll 8
        for (int w = 0; w < EWORDS; w++) cnt += __popc(g_wrecP[w * EN + c]);
        g_rowsumP[c] = (float)cnt;
        atomicMin(&g_rsmin, cnt);
        float s = 0.f;
#pragma unroll 4
        for (int i = 0; i < IN_; i++) s = __fadd_rn(s, g_wieP[(size_t)i * EN + c]);
        g_cs_wieP[c] = s;
        atomicMax(&g_cwie_max_u, __float_as_uint(s));  // s >= 0: bits monotone
    } else if (bid == 8) {
        if (tid < IN_) {
            const float4* r = reinterpret_cast<const float4*>(g_weiT + (size_t)tid * EN);
            float q = 0.f;
            for (int g = 0; g < 512; g++) {   // ascending e, exact chain
                float4 f = r[g];
                q = __fadd_rn(q, f.x); q = __fadd_rn(q, f.y);
                q = __fadd_rn(q, f.z); q = __fadd_rn(q, f.w);
            }
            g_cs_wei[tid] = q;
        }
    } else {
        const float4* x4 = reinterpret_cast<const float4*>(x);
        const int n4 = (TN * BN * EN) / 4;
        int i = (bid - 9) * 256 + tid;
        const int stride = 256 * 256;
        float m = 0.f;
        for (; i < n4; i += stride) {
            float4 f = x4[i];
            m = fmaxf(m, fmaxf(fmaxf(fabsf(f.x), fabsf(f.y)), fmaxf(fabsf(f.z), fabsf(f.w))));
        }
#pragma unroll
        for (int off = 16; off > 0; off >>= 1)
            m = fmaxf(m, __shfl_xor_sync(0xffffffffu, m, off));
        if (lane == 0) atomicMax(&g_xmax_u, __float_as_uint(m));
    }
}

// ---------------- main simulator: one CTA per batch, vectorized gathers, fused fill ----------------
__global__ __launch_bounds__(NT, 1)
void sim_kernel(const float* __restrict__ x, float* __restrict__ out)
{
    __shared__ uint32_t s_ez[2][EWORDS];
    __shared__ uint32_t s_iz[2][IWORDS];
    __shared__ __align__(16) unsigned char s_fb[2][16];
    __shared__ __align__(16) unsigned char s_cnt[2][16];

    const int t    = threadIdx.x;
    const int b    = blockIdx.x;
    const int warp = t >> 5, lane = t & 31;

    // exc neurons t + 512k as explicit scalars (c-index base 4t)
    float v0 = 0.f, v1 = 0.f, v2 = 0.f, v3 = 0.f;
    float c0 = 0.f, c1 = 0.f, c2 = 0.f, c3 = 0.f;
    float iv = 0.f, ii = 0.f;                      // inh neuron t (t < 256)

    const float cwei = (t < IN_) ? g_cs_wei[t] : 0.f;

    // absorbing-saturation invariant (exc-only, proven sufficient; see R8):
    const int g_ok =
        __fadd_rn((float)g_rsmin,
                  -__fadd_rn(__uint_as_float(g_cwie_max_u), __uint_as_float(g_xmax_u))) >= 13.0f;

    const uint4*  wrecP4 = reinterpret_cast<const uint4*>(g_wrecP);    // [w*512 + t]
    const float4* wieP4  = reinterpret_cast<const float4*>(g_wieP);    // [i*512 + t]
    const float4* weiT4  = reinterpret_cast<const float4*>(g_weiT);    // [i*512 + g]
    const float4* rsP4   = reinterpret_cast<const float4*>(g_rowsumP);
    const float4* cwP4   = reinterpret_cast<const float4*>(g_cs_wieP);

    if (t < EWORDS) s_ez[1][t] = 0u;
    if (t < IWORDS) s_iz[1][t] = 0u;
    __syncthreads();

    int pe_all = 0, pe_any = 0, pi_all = 0, pi_any = 0;
    int ts = TN;

    // prefetched x for current step
    float xn0 = x[(size_t)b * EN + t];
    float xn1 = x[(size_t)b * EN + t + 512];
    float xn2 = x[(size_t)b * EN + t + 1024];
    float xn3 = x[(size_t)b * EN + t + 1536];

    for (int st = 0; st < TN; st++) {
        const int wp = st & 1, rp = wp ^ 1;

        // ---- [a] recurrent term (integer-exact popcount) ----
        float rec0, rec1, rec2, rec3;
        if (pe_all) {
            float4 r = rsP4[t];
            rec0 = r.x; rec1 = r.y; rec2 = r.z; rec3 = r.w;
        } else if (!pe_any) {
            rec0 = rec1 = rec2 = rec3 = 0.f;
        } else {
            int a0 = 0, a1 = 0, a2 = 0, a3 = 0;
#pragma unroll 8
            for (int w = 0; w < EWORDS; w++) {
                uint32_t m = s_ez[rp][w];
                uint4 q = wrecP4[w * 512 + t];
                a0 += __popc(m & q.x); a1 += __popc(m & q.y);
                a2 += __popc(m & q.z); a3 += __popc(m & q.w);
            }
            rec0 = (float)a0; rec1 = (float)a1; rec2 = (float)a2; rec3 = (float)a3;
        }

        // ---- [a] inhibitory feedback (exact ascending-i chain) ----
        float inh0, inh1, inh2, inh3;
        if (pi_all) {
            float4 cwv = cwP4[t];
            inh0 = cwv.x; inh1 = cwv.y; inh2 = cwv.z; inh3 = cwv.w;
        } else if (!pi_any) {
            inh0 = inh1 = inh2 = inh3 = 0.f;
        } else {
            uint4 ma = *reinterpret_cast<const uint4*>(&s_iz[rp][0]);
            uint4 mb = *reinterpret_cast<const uint4*>(&s_iz[rp][4]);
            uint32_t mw[IWORDS] = {ma.x, ma.y, ma.z, ma.w, mb.x, mb.y, mb.z, mb.w};
            int icnt = __popc(ma.x) + __popc(ma.y) + __popc(ma.z) + __popc(ma.w)
                     + __popc(mb.x) + __popc(mb.y) + __popc(mb.z) + __popc(mb.w);
            inh0 = inh1 = inh2 = inh3 = 0.f;
            if (icnt <= 24) {
                for (int w = 0; w < IWORDS; w++) {
                    uint32_t m = mw[w];
                    while (m) {
                        int r = __ffs(m) - 1; m &= m - 1;
                        float4 wv = wieP4[(w * 32 + r) * 512 + t];
                        inh0 = __fadd_rn(inh0, wv.x); inh1 = __fadd_rn(inh1, wv.y);
                        inh2 = __fadd_rn(inh2, wv.z); inh3 = __fadd_rn(inh3, wv.w);
                    }
                }
            } else {
                // select-dense: unconditional float4 loads; fadd(s,+0.0) == s bit-exactly
                for (int w = 0; w < IWORDS; w++) {
                    uint32_t m = mw[w];
#pragma unroll 8
                    for (int r = 0; r < 32; r++) {
                        float4 wv = wieP4[(w * 32 + r) * 512 + t];
                        bool on = (m >> r) & 1u;
                        inh0 = __fadd_rn(inh0, on ? wv.x : 0.0f);
                        inh1 = __fadd_rn(inh1, on ? wv.y : 0.0f);
                        inh2 = __fadd_rn(inh2, on ? wv.z : 0.0f);
                        inh3 = __fadd_rn(inh3, on ? wv.w : 0.0f);
                    }
                }
            }
        }

        // ---- [b] excitatory update (JAX-exact rounding order) ----
        float id0 = __fadd_rn(c0, __fmul_rn(-0.2f, c0));
        float vd0 = __fadd_rn(v0, __fmul_rn(0.1f, __fadd_rn(__fsub_rn(0.f, v0), c0)));
        float id1 = __fadd_rn(c1, __fmul_rn(-0.2f, c1));
        float vd1 = __fadd_rn(v1, __fmul_rn(0.1f, __fadd_rn(__fsub_rn(0.f, v1), c1)));
        float id2 = __fadd_rn(c2, __fmul_rn(-0.2f, c2));
        float vd2 = __fadd_rn(v2, __fmul_rn(0.1f, __fadd_rn(__fsub_rn(0.f, v2), c2)));
        float id3 = __fadd_rn(c3, __fmul_rn(-0.2f, c3));
        float vd3 = __fadd_rn(v3, __fmul_rn(0.1f, __fadd_rn(__fsub_rn(0.f, v3), c3)));
        int z0 = __fsub_rn(vd0, 1.0f) > 0.f;
        int z1 = __fsub_rn(vd1, 1.0f) > 0.f;
        int z2 = __fsub_rn(vd2, 1.0f) > 0.f;
        int z3 = __fsub_rn(vd3, 1.0f) > 0.f;
        v0 = z0 ? 0.f : vd0;  v1 = z1 ? 0.f : vd1;
        v2 = z2 ? 0.f : vd2;  v3 = z3 ? 0.f : vd3;
        c0 = __fadd_rn(__fadd_rn(id0, __fsub_rn(xn0, inh0)), rec0);
        c1 = __fadd_rn(__fadd_rn(id1, __fsub_rn(xn1, inh1)), rec1);
        c2 = __fadd_rn(__fadd_rn(id2, __fsub_rn(xn2, inh2)), rec2);
        c3 = __fadd_rn(__fadd_rn(id3, __fsub_rn(xn3, inh3)), rec3);

        float* orow = out + ((size_t)st * BN + b) * EN;
        orow[t]        = z0 ? 1.f : 0.f;
        orow[t + 512]  = z1 ? 1.f : 0.f;
        orow[t + 1024] = z2 ? 1.f : 0.f;
        orow[t + 1536] = z3 ? 1.f : 0.f;

        if (st + 1 < TN) {
            const float* xb = x + ((size_t)(st + 1) * BN + b) * EN;
            xn0 = xb[t]; xn1 = xb[t + 512]; xn2 = xb[t + 1024]; xn3 = xb[t + 1536];
        }

        // inhibitory decay + spike from OLD inh state
        float ii_dec = __fadd_rn(ii, __fmul_rn(-0.2f, ii));
        float vi_dec = __fadd_rn(iv, __fmul_rn(0.1f, __fadd_rn(__fsub_rn(0.f, iv), ii)));
        int zi = __fsub_rn(vi_dec, 1.0f) > 0.f;   // t>=256: state stays 0 -> zi=0
        iv = zi ? 0.f : vi_dec;

        int stable = g_ok && z0 && z1 && z2 && z3
                   && (c0 >= 64.f) && (c1 >= 64.f) && (c2 >= 64.f) && (c3 >= 64.f);

        // ---- [c] publish spikes + per-warp flag & count bytes ----
        uint32_t eb0 = __ballot_sync(0xffffffffu, z0);
        uint32_t eb1 = __ballot_sync(0xffffffffu, z1);
        uint32_t eb2 = __ballot_sync(0xffffffffu, z2);
        uint32_t eb3 = __ballot_sync(0xffffffffu, z3);
        uint32_t ibal = __ballot_sync(0xffffffffu, zi);
        uint32_t sbal = __ballot_sync(0xffffffffu, stable);
        if (lane == 0) {
            s_ez[wp][warp]      = eb0;
            s_ez[wp][16 + warp] = eb1;
            s_ez[wp][32 + warp] = eb2;
            s_ez[wp][48 + warp] = eb3;
            uint32_t ea = ((eb0 & eb1 & eb2 & eb3) == 0xffffffffu) ? 1u : 0u;
            uint32_t ey = ((eb0 | eb1 | eb2 | eb3) != 0u) ? 1u : 0u;
            uint32_t sa = (sbal == 0xffffffffu) ? 1u : 0u;
            uint32_t ia, iy;
            if (warp < IWORDS) {
                s_iz[wp][warp] = ibal;
                ia = (ibal == 0xffffffffu) ? 1u : 0u;
                iy = (ibal != 0u) ? 1u : 0u;
            } else { ia = 1u; iy = 0u; }
            s_fb[wp][warp]  = (unsigned char)(ea | (ey << 1) | (ia << 2) | (iy << 3) | (sa << 4));
            s_cnt[wp][warp] = (unsigned char)(__popc(eb0) + __popc(eb1) + __popc(eb2) + __popc(eb3));
        }
        __syncthreads();   // the only barrier per step

        uint4 f = *reinterpret_cast<const uint4*>(&s_fb[wp][0]);
        uint32_t fand = f.x & f.y & f.z & f.w;
        uint32_t forr = f.x | f.y | f.z | f.w;
        fand &= fand >> 16; fand &= fand >> 8;
        forr |= forr >> 16; forr |= forr >> 8;
        int ne_all = fand & 1;        int ne_any = (forr >> 1) & 1;
        int ni_all = (fand >> 2) & 1; int ni_any = (forr >> 3) & 1;

        if ((fand >> 4) & 1) { ts = st + 1; break; }   // absorbing saturation (uniform)

        uint4 cc = *reinterpret_cast<const uint4*>(&s_cnt[wp][0]);
        unsigned int ec = 0u;
        ec = __dp4a(cc.x, 0x01010101u, ec); ec = __dp4a(cc.y, 0x01010101u, ec);
        ec = __dp4a(cc.z, 0x01010101u, ec); ec = __dp4a(cc.w, 0x01010101u, ec);
        int ecnt = (int)ec;

        // ---- [d] inhibitory current update with NEW exc spikes (exact ascending-e chain) ----
        if (t < IN_) {
            float xi;
            if (ne_all)       xi = cwei;
            else if (!ne_any) xi = 0.f;
            else if (ecnt <= 24) {
                xi = 0.f;
                for (int w = 0; w < EWORDS; w++) {
                    uint32_t m = s_ez[wp][w];
                    while (m) {
                        int r = __ffs(m) - 1; m &= m - 1;
                        xi = __fadd_rn(xi, g_weiT[(size_t)t * EN + w * 32 + r]);
                    }
                }
            } else {
                xi = 0.f;
                for (int w = 0; w < EWORDS; w++) {
                    uint32_t m = s_ez[wp][w];
#pragma unroll
                    for (int q = 0; q < 8; q++) {      // e = 32w + 4q + r, ascending
                        float4 wv = weiT4[t * 512 + w * 8 + q];
                        int sh = q * 4;
                        xi = __fadd_rn(xi, ((m >> (sh + 0)) & 1u) ? wv.x : 0.0f);
                        xi = __fadd_rn(xi, ((m >> (sh + 1)) & 1u) ? wv.y : 0.0f);
                        xi = __fadd_rn(xi, ((m >> (sh + 2)) & 1u) ? wv.z : 0.0f);
                        xi = __fadd_rn(xi, ((m >> (sh + 3)) & 1u) ? wv.w : 0.0f);
                    }
                }
            }
            ii = __fadd_rn(ii_dec, xi);
        }
        pe_all = ne_all; pe_any = ne_any; pi_all = ni_all; pi_any = ni_any;
    }

    // ---- fused fill: rows [ts, TN) of this batch are all ones ----
    const float4 ones = make_float4(1.f, 1.f, 1.f, 1.f);
    for (int r = ts; r < TN; r++) {
        float4* o4 = reinterpret_cast<float4*>(out + ((size_t)r * BN + b) * EN);
        __stcs(&o4[t], ones);   // 512 threads x 16B = full 2048-float row
    }
}

extern "C" void kernel_launch(void* const* d_in, const int* in_sizes, int n_in,
                              void* d_out, int out_size)
{
    const float* x     = (const float*)d_in[0];  // [T,B,E]
    // d_in[1] = w_in (identity) -- exact pass-through, unused
    const float* w_rec = (const float*)d_in[2];  // [E,E]
    const float* w_ei  = (const float*)d_in[3];  // [E,I]
    const float* w_ie  = (const float*)d_in[4];  // [I,E]
    float* out = (float*)d_out;

    prep1<<<1536, 256>>>(w_rec, w_ie, w_ei);
    prep2<<<9 + 256, 256>>>(x);
    sim_kernel<<<BN, NT>>>(x, out);
}